// round 8
// baseline (speedup 1.0000x reference)
#include <cuda_runtime.h>

#define B_    4096
#define NNODE 64
#define FIN   67
#define C1    64
#define C2    32
#define DFP   2048
#define H1D   400
#define H2D   64
#define NEDGE 512

typedef unsigned long long u64;

// ---------------- scratch (device globals; no allocations allowed) ----------------
__device__ float g_P [NNODE * NNODE];            // propagation matrix P[d][s]
__device__ float g_Y1[B_ * NNODE * C1];          // X @ W1^T
__device__ float g_G1[B_ * NNODE * C1];          // P @ Y1 + b1 (pre-BN)
__device__ float g_Z2[B_ * NNODE * C2];          // relu(bn(G1)) @ W2^T
__device__ float g_G2[B_ * NNODE * C2];          // P @ Z2 + b2 (pre-BN)
__device__ float g_pool[B_ * C2];
__device__ float g_H1[B_ * H1D];
__device__ float g_H2[B_ * H2D];
__device__ float g_sum1[NNODE], g_ssq1[NNODE], g_sum2[NNODE], g_ssq2[NNODE];
__device__ float g_a1[NNODE], g_c1[NNODE], g_a2[NNODE], g_c2[NNODE];

// ---------------- packed f32x2 helpers ----------------
__device__ __forceinline__ void fma2(u64& d, u64 a, u64 b) {
    asm("fma.rn.f32x2 %0, %1, %2, %0;" : "+l"(d) : "l"(a), "l"(b));
}
__device__ __forceinline__ u64 dup2(float x) {
    u64 r; asm("mov.b64 %0, {%1, %1};" : "=l"(r) : "f"(x)); return r;
}
__device__ __forceinline__ float2 unpk(u64 v) {
    float2 r; asm("mov.b64 {%0, %1}, %2;" : "=f"(r.x), "=f"(r.y) : "l"(v)); return r;
}

// ---------------- K0: build P from edge list, zero stats ----------------
__global__ void k_prep(const int* __restrict__ el) {
    __shared__ float deg[NNODE];
    __shared__ float dinv[NNODE];
    __shared__ float Ps[NNODE * NNODE];
    int t = threadIdx.x;
    if (t < NNODE) deg[t] = 0.f;
    for (int i = t; i < NNODE * NNODE; i += 256) Ps[i] = 0.f;
    __syncthreads();
    for (int i = t; i < NEDGE + NNODE; i += 256) {
        int d = (i < NEDGE) ? el[NEDGE + i] : (i - NEDGE);
        atomicAdd(&deg[d], 1.f);
    }
    __syncthreads();
    if (t < NNODE) dinv[t] = (deg[t] > 0.f) ? rsqrtf(deg[t]) : 0.f;
    __syncthreads();
    for (int i = t; i < NEDGE + NNODE; i += 256) {
        int s = (i < NEDGE) ? el[i] : (i - NEDGE);
        int d = (i < NEDGE) ? el[NEDGE + i] : (i - NEDGE);
        atomicAdd(&Ps[d * NNODE + s], dinv[s] * dinv[d]);
    }
    __syncthreads();
    for (int i = t; i < NNODE * NNODE; i += 256) g_P[i] = Ps[i];
    if (t < NNODE) { g_sum1[t] = 0.f; g_ssq1[t] = 0.f; g_sum2[t] = 0.f; g_ssq2[t] = 0.f; }
}

// ---------------- K1: Y1 = X @ W1^T  (M=262144, K=67, N=64) ----------------
__global__ void k_gemm1(const float* __restrict__ X, const float* __restrict__ W1) {
    __shared__ __align__(16) float As[FIN * 68];   // As[k][m], m padded to 68
    __shared__ __align__(16) float Ws[FIN * 68];   // Ws[k][n]
    int t = threadIdx.x;
    int m0 = blockIdx.x * 64;
    const float* Xt = X + (size_t)m0 * FIN;
    for (int i = t; i < 64 * FIN; i += 256) {
        int r = i / FIN, k = i - r * FIN;
        As[k * 68 + r] = Xt[i];
    }
    for (int i = t; i < 64 * FIN; i += 256) {
        int n = i / FIN, k = i - n * FIN;
        Ws[k * 68 + n] = W1[i];
    }
    __syncthreads();
    int tm = (t >> 4) * 4, tn = (t & 15) * 4;
    float acc[4][4] = {};
    for (int k = 0; k < FIN; k++) {
        float4 a = *reinterpret_cast<const float4*>(&As[k * 68 + tm]);
        float4 b = *reinterpret_cast<const float4*>(&Ws[k * 68 + tn]);
        acc[0][0] = fmaf(a.x, b.x, acc[0][0]); acc[0][1] = fmaf(a.x, b.y, acc[0][1]);
        acc[0][2] = fmaf(a.x, b.z, acc[0][2]); acc[0][3] = fmaf(a.x, b.w, acc[0][3]);
        acc[1][0] = fmaf(a.y, b.x, acc[1][0]); acc[1][1] = fmaf(a.y, b.y, acc[1][1]);
        acc[1][2] = fmaf(a.y, b.z, acc[1][2]); acc[1][3] = fmaf(a.y, b.w, acc[1][3]);
        acc[2][0] = fmaf(a.z, b.x, acc[2][0]); acc[2][1] = fmaf(a.z, b.y, acc[2][1]);
        acc[2][2] = fmaf(a.z, b.z, acc[2][2]); acc[2][3] = fmaf(a.z, b.w, acc[2][3]);
        acc[3][0] = fmaf(a.w, b.x, acc[3][0]); acc[3][1] = fmaf(a.w, b.y, acc[3][1]);
        acc[3][2] = fmaf(a.w, b.z, acc[3][2]); acc[3][3] = fmaf(a.w, b.w, acc[3][3]);
    }
    #pragma unroll
    for (int i = 0; i < 4; i++) {
        float4 v = make_float4(acc[i][0], acc[i][1], acc[i][2], acc[i][3]);
        *reinterpret_cast<float4*>(&g_Y1[(size_t)(m0 + tm + i) * 64 + tn]) = v;
    }
}

// ---------------- K2: G1[b] = P @ Y1[b] + b1, with BN1 stats epilogue ----------------
__global__ void k_pgemm1(const float* __restrict__ b1) {
    __shared__ __align__(16) float Ps[4096];
    __shared__ __align__(16) float Ys[4096];
    int b = blockIdx.x, t = threadIdx.x;
    const float* src = g_Y1 + (size_t)b * 4096;
    for (int i = t; i < 4096; i += 256) { Ps[i] = g_P[i]; Ys[i] = src[i]; }
    __syncthreads();
    int d0 = (t >> 4) * 4, o0 = (t & 15) * 4;
    float acc[4][4] = {};
    #pragma unroll 4
    for (int s = 0; s < 64; s++) {
        float4 y = *reinterpret_cast<const float4*>(&Ys[s * 64 + o0]);
        #pragma unroll
        for (int i = 0; i < 4; i++) {
            float p = Ps[(d0 + i) * 64 + s];
            acc[i][0] = fmaf(p, y.x, acc[i][0]);
            acc[i][1] = fmaf(p, y.y, acc[i][1]);
            acc[i][2] = fmaf(p, y.z, acc[i][2]);
            acc[i][3] = fmaf(p, y.w, acc[i][3]);
        }
    }
    float4 bb = *reinterpret_cast<const float4*>(&b1[o0]);
    float* out = g_G1 + (size_t)b * 4096;
    float sums[4], ssqs[4];
    #pragma unroll
    for (int i = 0; i < 4; i++) {
        float v0 = acc[i][0] + bb.x, v1 = acc[i][1] + bb.y;
        float v2 = acc[i][2] + bb.z, v3 = acc[i][3] + bb.w;
        *reinterpret_cast<float4*>(&out[(d0 + i) * 64 + o0]) = make_float4(v0, v1, v2, v3);
        sums[i] = (v0 + v1) + (v2 + v3);
        ssqs[i] = fmaf(v0, v0, fmaf(v1, v1, fmaf(v2, v2, v3 * v3)));
    }
    #pragma unroll
    for (int off = 8; off >= 1; off >>= 1) {
        #pragma unroll
        for (int i = 0; i < 4; i++) {
            sums[i] += __shfl_xor_sync(0xffffffffu, sums[i], off);
            ssqs[i] += __shfl_xor_sync(0xffffffffu, ssqs[i], off);
        }
    }
    if ((t & 15) == 0) {
        #pragma unroll
        for (int i = 0; i < 4; i++) {
            atomicAdd(&g_sum1[d0 + i], sums[i]);
            atomicAdd(&g_ssq1[d0 + i], ssqs[i]);
        }
    }
}

// ---------------- finalize BN scale/shift ----------------
__global__ void k_bnfin(int stage, const float* __restrict__ gamma,
                        const float* __restrict__ beta, float invn) {
    int t = threadIdx.x;
    if (t < NNODE) {
        const float* sum = stage ? g_sum2 : g_sum1;
        const float* ssq = stage ? g_ssq2 : g_ssq1;
        float* a = stage ? g_a2 : g_a1;
        float* c = stage ? g_c2 : g_c1;
        float m = sum[t] * invn;
        float v = ssq[t] * invn - m * m;
        float r = rsqrtf(v + 1e-5f);
        float aa = gamma[t] * r;
        a[t] = aa;
        c[t] = beta[t] - m * aa;
    }
}

// ---------------- K3: Z2[b] = relu(bn(G1[b])) @ W2^T ----------------
__global__ void k_gemm2(const float* __restrict__ W2) {
    __shared__ float a1s[64], c1s[64];
    __shared__ __align__(16) float G1s[4096];
    __shared__ __align__(16) float W2t[64 * 36];   // W2t[o][j], j padded to 36
    int b = blockIdx.x, t = threadIdx.x;
    if (t < 64) { a1s[t] = g_a1[t]; c1s[t] = g_c1[t]; }
    __syncthreads();
    const float* src = g_G1 + (size_t)b * 4096;
    for (int i = t; i < 4096; i += 256) {
        int d = i >> 6;
        G1s[i] = fmaxf(fmaf(src[i], a1s[d], c1s[d]), 0.f);
    }
    for (int i = t; i < 2048; i += 256) {
        int j = i >> 6, o = i & 63;
        W2t[o * 36 + j] = W2[i];
    }
    __syncthreads();
    int d0 = (t >> 3) * 2, j0 = (t & 7) * 4;
    float acc[2][4] = {};
    #pragma unroll 4
    for (int o = 0; o < 64; o++) {
        float4 w = *reinterpret_cast<const float4*>(&W2t[o * 36 + j0]);
        float gA = G1s[d0 * 64 + o];
        float gB = G1s[d0 * 64 + 64 + o];
        acc[0][0] = fmaf(gA, w.x, acc[0][0]); acc[0][1] = fmaf(gA, w.y, acc[0][1]);
        acc[0][2] = fmaf(gA, w.z, acc[0][2]); acc[0][3] = fmaf(gA, w.w, acc[0][3]);
        acc[1][0] = fmaf(gB, w.x, acc[1][0]); acc[1][1] = fmaf(gB, w.y, acc[1][1]);
        acc[1][2] = fmaf(gB, w.z, acc[1][2]); acc[1][3] = fmaf(gB, w.w, acc[1][3]);
    }
    float* out = g_Z2 + (size_t)b * 2048;
    *reinterpret_cast<float4*>(&out[d0 * 32 + j0]) =
        make_float4(acc[0][0], acc[0][1], acc[0][2], acc[0][3]);
    *reinterpret_cast<float4*>(&out[(d0 + 1) * 32 + j0]) =
        make_float4(acc[1][0], acc[1][1], acc[1][2], acc[1][3]);
}

// ---------------- K4: G2[b] = P @ Z2[b] + b2, with BN2 stats epilogue ----------------
__global__ void k_pgemm2(const float* __restrict__ b2) {
    __shared__ __align__(16) float Ps[4096];
    __shared__ __align__(16) float Zs[2048];
    int b = blockIdx.x, t = threadIdx.x;
    const float* src = g_Z2 + (size_t)b * 2048;
    for (int i = t; i < 4096; i += 256) Ps[i] = g_P[i];
    for (int i = t; i < 2048; i += 256) Zs[i] = src[i];
    __syncthreads();
    int d0 = (t >> 4) * 4, j0 = (t & 15) * 2;
    float acc[4][2] = {};
    #pragma unroll 4
    for (int s = 0; s < 64; s++) {
        float2 z = *reinterpret_cast<const float2*>(&Zs[s * 32 + j0]);
        #pragma unroll
        for (int i = 0; i < 4; i++) {
            float p = Ps[(d0 + i) * 64 + s];
            acc[i][0] = fmaf(p, z.x, acc[i][0]);
            acc[i][1] = fmaf(p, z.y, acc[i][1]);
        }
    }
    float2 bb = *reinterpret_cast<const float2*>(&b2[j0]);
    float* out = g_G2 + (size_t)b * 2048;
    float sums[4], ssqs[4];
    #pragma unroll
    for (int i = 0; i < 4; i++) {
        float v0 = acc[i][0] + bb.x, v1 = acc[i][1] + bb.y;
        *reinterpret_cast<float2*>(&out[(d0 + i) * 32 + j0]) = make_float2(v0, v1);
        sums[i] = v0 + v1;
        ssqs[i] = fmaf(v0, v0, v1 * v1);
    }
    #pragma unroll
    for (int off = 8; off >= 1; off >>= 1) {
        #pragma unroll
        for (int i = 0; i < 4; i++) {
            sums[i] += __shfl_xor_sync(0xffffffffu, sums[i], off);
            ssqs[i] += __shfl_xor_sync(0xffffffffu, ssqs[i], off);
        }
    }
    if ((t & 15) == 0) {
        #pragma unroll
        for (int i = 0; i < 4; i++) {
            atomicAdd(&g_sum2[d0 + i], sums[i]);
            atomicAdd(&g_ssq2[d0 + i], ssqs[i]);
        }
    }
}

// ---------------- K5: bn + relu + max-pool over nodes ----------------
__global__ void k_pool() {
    __shared__ float a2s[64], c2s[64];
    int t = threadIdx.x;
    if (t < 64) { a2s[t] = g_a2[t]; c2s[t] = g_c2[t]; }
    __syncthreads();
    int bl = t >> 5, j = t & 31;
    int b = blockIdx.x * 8 + bl;
    const float* src = g_G2 + (size_t)b * 2048 + j;
    float m = 0.f;   // relu outputs are >= 0
    #pragma unroll 8
    for (int d = 0; d < 64; d++) {
        float v = fmaxf(fmaf(src[d * 32], a2s[d], c2s[d]), 0.f);
        m = fmaxf(m, v);
    }
    g_pool[b * 32 + j] = m;
}

// ---------------- MLP1 (FFMA2, 128x128 tile): H1 = relu(xf @ Wl1^T + bl1) ----------
// A: [4096 x 2048], Bw: [400 x 2048] -> C: [4096 x 400]
__global__ __launch_bounds__(256, 2)
void k_mlp1(const float* __restrict__ A, const float* __restrict__ Bw,
            const float* __restrict__ bias) {
    __shared__ __align__(16) float As[16 * 132];   // As[k][m], 128 m padded to 132
    __shared__ __align__(16) float Bs[16 * 132];   // Bs[k][n]
    __shared__ float bsh[128];

    int t = threadIdx.x;
    int m0 = blockIdx.x * 128, n0 = blockIdx.y * 128;

    if (t < 128) bsh[t] = (n0 + t < H1D) ? bias[n0 + t] : 0.f;

    int tmp = (t >> 4) * 8;       // 8 m-rows (4 pairs)
    int tn  = (t & 15) * 8;       // 8 n-cols
    u64 acc[4][8] = {};

    for (int k0 = 0; k0 < DFP; k0 += 16) {
        #pragma unroll
        for (int rep = 0; rep < 2; rep++) {
            int idx = t + 256 * rep;        // float4 index, 0..511
            int row = idx >> 2;             // 0..127
            int k4  = (idx & 3) * 4;        // 0,4,8,12
            float4 av = *reinterpret_cast<const float4*>(&A[(size_t)(m0 + row) * DFP + k0 + k4]);
            As[(k4 + 0) * 132 + row] = av.x;
            As[(k4 + 1) * 132 + row] = av.y;
            As[(k4 + 2) * 132 + row] = av.z;
            As[(k4 + 3) * 132 + row] = av.w;
            float4 bv = make_float4(0.f, 0.f, 0.f, 0.f);
            if (n0 + row < H1D)
                bv = *reinterpret_cast<const float4*>(&Bw[(size_t)(n0 + row) * DFP + k0 + k4]);
            Bs[(k4 + 0) * 132 + row] = bv.x;
            Bs[(k4 + 1) * 132 + row] = bv.y;
            Bs[(k4 + 2) * 132 + row] = bv.z;
            Bs[(k4 + 3) * 132 + row] = bv.w;
        }
        __syncthreads();
        #pragma unroll
        for (int kk = 0; kk < 16; kk++) {
            ulonglong2 a01 = *reinterpret_cast<const ulonglong2*>(&As[kk * 132 + tmp]);
            ulonglong2 a23 = *reinterpret_cast<const ulonglong2*>(&As[kk * 132 + tmp + 4]);
            float4 b0 = *reinterpret_cast<const float4*>(&Bs[kk * 132 + tn]);
            float4 b1 = *reinterpret_cast<const float4*>(&Bs[kk * 132 + tn + 4]);
            u64 bd[8];
            bd[0] = dup2(b0.x); bd[1] = dup2(b0.y); bd[2] = dup2(b0.z); bd[3] = dup2(b0.w);
            bd[4] = dup2(b1.x); bd[5] = dup2(b1.y); bd[6] = dup2(b1.z); bd[7] = dup2(b1.w);
            #pragma unroll
            for (int j = 0; j < 8; j++) {
                fma2(acc[0][j], a01.x, bd[j]);
                fma2(acc[1][j], a01.y, bd[j]);
                fma2(acc[2][j], a23.x, bd[j]);
                fma2(acc[3][j], a23.y, bd[j]);
            }
        }
        __syncthreads();
    }

    // epilogue: bias + relu, guarded stores
    #pragma unroll
    for (int mp = 0; mp < 4; mp++) {
        int r0 = m0 + tmp + 2 * mp;
        float* c0 = g_H1 + (size_t)r0 * H1D;
        float* c1 = c0 + H1D;
        #pragma unroll
        for (int j = 0; j < 8; j++) {
            int col = n0 + tn + j;
            if (col < H1D) {
                float2 p = unpk(acc[mp][j]);
                float bv = bsh[tn + j];
                c0[col] = fmaxf(p.x + bv, 0.f);
                c1[col] = fmaxf(p.y + bv, 0.f);
            }
        }
    }
}

// ---------------- MLP2 (scalar): H2 = relu(H1 @ Wl2^T + bl2) ----------------
__global__ void k_mlp2(const float* __restrict__ Bw, const float* __restrict__ bias) {
    __shared__ __align__(16) float As[16 * 68];
    __shared__ __align__(16) float Bs[16 * 68];
    const float* A = g_H1;
    float* C = g_H2;
    int m0 = blockIdx.x * 64;
    int t = threadIdx.x;
    int tm = (t >> 4) * 4, tn = (t & 15) * 4;
    float acc[4][4] = {};
    for (int k0 = 0; k0 < H1D; k0 += 16) {
        for (int i = t; i < 1024; i += 256) {
            int r = i >> 4, kk = i & 15;
            As[kk * 68 + r] = A[(size_t)(m0 + r) * H1D + k0 + kk];
            Bs[kk * 68 + r] = Bw[(size_t)r * H1D + k0 + kk];
        }
        __syncthreads();
        #pragma unroll
        for (int kk = 0; kk < 16; kk++) {
            float4 a = *reinterpret_cast<const float4*>(&As[kk * 68 + tm]);
            float4 b = *reinterpret_cast<const float4*>(&Bs[kk * 68 + tn]);
            acc[0][0] = fmaf(a.x, b.x, acc[0][0]); acc[0][1] = fmaf(a.x, b.y, acc[0][1]);
            acc[0][2] = fmaf(a.x, b.z, acc[0][2]); acc[0][3] = fmaf(a.x, b.w, acc[0][3]);
            acc[1][0] = fmaf(a.y, b.x, acc[1][0]); acc[1][1] = fmaf(a.y, b.y, acc[1][1]);
            acc[1][2] = fmaf(a.y, b.z, acc[1][2]); acc[1][3] = fmaf(a.y, b.w, acc[1][3]);
            acc[2][0] = fmaf(a.z, b.x, acc[2][0]); acc[2][1] = fmaf(a.z, b.y, acc[2][1]);
            acc[2][2] = fmaf(a.z, b.z, acc[2][2]); acc[2][3] = fmaf(a.z, b.w, acc[2][3]);
            acc[3][0] = fmaf(a.w, b.x, acc[3][0]); acc[3][1] = fmaf(a.w, b.y, acc[3][1]);
            acc[3][2] = fmaf(a.w, b.z, acc[3][2]); acc[3][3] = fmaf(a.w, b.w, acc[3][3]);
        }
        __syncthreads();
    }
    #pragma unroll
    for (int i = 0; i < 4; i++) {
        int row = m0 + tm + i;
        #pragma unroll
        for (int j = 0; j < 4; j++) {
            int col = tn + j;
            C[(size_t)row * H2D + col] = fmaxf(acc[i][j] + __ldg(&bias[col]), 0.f);
        }
    }
}

// ---------------- final: out = [pool, H2] @ Wfc^T + bfc ----------------
__global__ void k_final(const float* __restrict__ Wfc, const float* __restrict__ bfc,
                        float* __restrict__ out) {
    __shared__ float Ws[192];
    int t = threadIdx.x;
    if (t < 192) Ws[t] = Wfc[t];
    __syncthreads();
    int b = blockIdx.x * 256 + t;
    float a0 = __ldg(&bfc[0]), a1 = __ldg(&bfc[1]);
    const float* pp = g_pool + b * 32;
    const float* hh = g_H2 + b * 64;
    #pragma unroll
    for (int j = 0; j < 32; j++) {
        float v = pp[j];
        a0 = fmaf(v, Ws[j], a0);
        a1 = fmaf(v, Ws[96 + j], a1);
    }
    #pragma unroll
    for (int j = 0; j < 64; j++) {
        float v = hh[j];
        a0 = fmaf(v, Ws[32 + j], a0);
        a1 = fmaf(v, Ws[128 + j], a1);
    }
    out[b * 2]     = a0;
    out[b * 2 + 1] = a1;
}

// ---------------- launch ----------------
extern "C" void kernel_launch(void* const* d_in, const int* in_sizes, int n_in,
                              void* d_out, int out_size) {
    const float* xf  = (const float*)d_in[0];
    const float* xn  = (const float*)d_in[1];
    const int*   el  = (const int*)  d_in[2];
    const float* W1  = (const float*)d_in[3];
    const float* b1  = (const float*)d_in[4];
    const float* g1  = (const float*)d_in[5];
    const float* be1 = (const float*)d_in[6];
    const float* W2  = (const float*)d_in[7];
    const float* b2  = (const float*)d_in[8];
    const float* g2  = (const float*)d_in[9];
    const float* be2 = (const float*)d_in[10];
    const float* Wl1 = (const float*)d_in[11];
    const float* bl1 = (const float*)d_in[12];
    const float* Wl2 = (const float*)d_in[13];
    const float* bl2 = (const float*)d_in[14];
    const float* Wfc = (const float*)d_in[15];
    const float* bfc = (const float*)d_in[16];
    float* out = (float*)d_out;

    k_prep<<<1, 256>>>(el);

    // graph path (stats fused into pgemm epilogues)
    k_gemm1<<<(B_ * NNODE) / 64, 256>>>(xn, W1);
    k_pgemm1<<<B_, 256>>>(b1);
    k_bnfin<<<1, 64>>>(0, g1, be1, 1.0f / (float)(B_ * C1));
    k_gemm2<<<B_, 256>>>(W2);
    k_pgemm2<<<B_, 256>>>(b2);
    k_bnfin<<<1, 64>>>(1, g2, be2, 1.0f / (float)(B_ * C2));
    k_pool<<<B_ / 8, 256>>>();

    // fingerprint MLP path
    k_mlp1<<<dim3(B_ / 128, (H1D + 127) / 128), 256>>>(xf, Wl1, bl1);
    k_mlp2<<<B_ / 64, 256>>>(Wl2, bl2);

    k_final<<<B_ / 256, 256>>>(Wfc, bfc, out);
}

// round 10
// speedup vs baseline: 1.4614x; 1.4614x over previous
#include <cuda_runtime.h>

#define B_    4096
#define NNODE 64
#define FIN   67
#define C1    64
#define C2    32
#define DFP   2048
#define H1D   400
#define H2D   64
#define NEDGE 512

// ---------------- scratch (device globals; no allocations allowed) ----------------
__device__ float g_P [NNODE * NNODE];            // propagation matrix P[d][s]
__device__ float g_Y1[B_ * NNODE * C1];          // X @ W1^T
__device__ float g_G1[B_ * NNODE * C1];          // P @ Y1 + b1 (pre-BN)
__device__ float g_Z2[B_ * NNODE * C2];          // relu(bn(G1)) @ W2^T
__device__ float g_G2[B_ * NNODE * C2];          // P @ Z2 + b2 (pre-BN)
__device__ float g_pool[B_ * C2];
__device__ float g_H1[B_ * H1D];
__device__ float g_H2[B_ * H2D];
__device__ float g_sum1[NNODE], g_ssq1[NNODE], g_sum2[NNODE], g_ssq2[NNODE];

// ---------------- K0: build P from edge list, zero stats ----------------
__global__ void k_prep(const int* __restrict__ el) {
    __shared__ float deg[NNODE];
    __shared__ float dinv[NNODE];
    __shared__ float Ps[NNODE * NNODE];
    int t = threadIdx.x;
    if (t < NNODE) deg[t] = 0.f;
    for (int i = t; i < NNODE * NNODE; i += 256) Ps[i] = 0.f;
    __syncthreads();
    for (int i = t; i < NEDGE + NNODE; i += 256) {
        int d = (i < NEDGE) ? el[NEDGE + i] : (i - NEDGE);
        atomicAdd(&deg[d], 1.f);
    }
    __syncthreads();
    if (t < NNODE) dinv[t] = (deg[t] > 0.f) ? rsqrtf(deg[t]) : 0.f;
    __syncthreads();
    for (int i = t; i < NEDGE + NNODE; i += 256) {
        int s = (i < NEDGE) ? el[i] : (i - NEDGE);
        int d = (i < NEDGE) ? el[NEDGE + i] : (i - NEDGE);
        atomicAdd(&Ps[d * NNODE + s], dinv[s] * dinv[d]);
    }
    __syncthreads();
    for (int i = t; i < NNODE * NNODE; i += 256) g_P[i] = Ps[i];
    if (t < NNODE) { g_sum1[t] = 0.f; g_ssq1[t] = 0.f; g_sum2[t] = 0.f; g_ssq2[t] = 0.f; }
}

// ---------------- K1: Y1 = X @ W1^T  (M=262144, K=67, N=64) ----------------
__global__ void k_gemm1(const float* __restrict__ X, const float* __restrict__ W1) {
    __shared__ __align__(16) float As[FIN * 68];   // As[k][m], m padded to 68
    __shared__ __align__(16) float Ws[FIN * 68];   // Ws[k][n]
    int t = threadIdx.x;
    int m0 = blockIdx.x * 64;
    const float* Xt = X + (size_t)m0 * FIN;
    for (int i = t; i < 64 * FIN; i += 256) {
        int r = i / FIN, k = i - r * FIN;
        As[k * 68 + r] = Xt[i];
    }
    for (int i = t; i < 64 * FIN; i += 256) {
        int n = i / FIN, k = i - n * FIN;
        Ws[k * 68 + n] = W1[i];
    }
    __syncthreads();
    int tm = (t >> 4) * 4, tn = (t & 15) * 4;
    float acc[4][4] = {};
    for (int k = 0; k < FIN; k++) {
        float4 a = *reinterpret_cast<const float4*>(&As[k * 68 + tm]);
        float4 b = *reinterpret_cast<const float4*>(&Ws[k * 68 + tn]);
        acc[0][0] = fmaf(a.x, b.x, acc[0][0]); acc[0][1] = fmaf(a.x, b.y, acc[0][1]);
        acc[0][2] = fmaf(a.x, b.z, acc[0][2]); acc[0][3] = fmaf(a.x, b.w, acc[0][3]);
        acc[1][0] = fmaf(a.y, b.x, acc[1][0]); acc[1][1] = fmaf(a.y, b.y, acc[1][1]);
        acc[1][2] = fmaf(a.y, b.z, acc[1][2]); acc[1][3] = fmaf(a.y, b.w, acc[1][3]);
        acc[2][0] = fmaf(a.z, b.x, acc[2][0]); acc[2][1] = fmaf(a.z, b.y, acc[2][1]);
        acc[2][2] = fmaf(a.z, b.z, acc[2][2]); acc[2][3] = fmaf(a.z, b.w, acc[2][3]);
        acc[3][0] = fmaf(a.w, b.x, acc[3][0]); acc[3][1] = fmaf(a.w, b.y, acc[3][1]);
        acc[3][2] = fmaf(a.w, b.z, acc[3][2]); acc[3][3] = fmaf(a.w, b.w, acc[3][3]);
    }
    #pragma unroll
    for (int i = 0; i < 4; i++) {
        float4 v = make_float4(acc[i][0], acc[i][1], acc[i][2], acc[i][3]);
        *reinterpret_cast<float4*>(&g_Y1[(size_t)(m0 + tm + i) * 64 + tn]) = v;
    }
}

// ---------------- K2: G1[b] = P @ Y1[b] + b1, with BN1 stats epilogue ----------------
__global__ void k_pgemm1(const float* __restrict__ b1) {
    __shared__ __align__(16) float Ps[4096];
    __shared__ __align__(16) float Ys[4096];
    int b = blockIdx.x, t = threadIdx.x;
    const float* src = g_Y1 + (size_t)b * 4096;
    for (int i = t; i < 4096; i += 256) { Ps[i] = g_P[i]; Ys[i] = src[i]; }
    __syncthreads();
    int d0 = (t >> 4) * 4, o0 = (t & 15) * 4;
    float acc[4][4] = {};
    #pragma unroll 4
    for (int s = 0; s < 64; s++) {
        float4 y = *reinterpret_cast<const float4*>(&Ys[s * 64 + o0]);
        #pragma unroll
        for (int i = 0; i < 4; i++) {
            float p = Ps[(d0 + i) * 64 + s];
            acc[i][0] = fmaf(p, y.x, acc[i][0]);
            acc[i][1] = fmaf(p, y.y, acc[i][1]);
            acc[i][2] = fmaf(p, y.z, acc[i][2]);
            acc[i][3] = fmaf(p, y.w, acc[i][3]);
        }
    }
    float4 bb = *reinterpret_cast<const float4*>(&b1[o0]);
    float* out = g_G1 + (size_t)b * 4096;
    float sums[4], ssqs[4];
    #pragma unroll
    for (int i = 0; i < 4; i++) {
        float v0 = acc[i][0] + bb.x, v1 = acc[i][1] + bb.y;
        float v2 = acc[i][2] + bb.z, v3 = acc[i][3] + bb.w;
        *reinterpret_cast<float4*>(&out[(d0 + i) * 64 + o0]) = make_float4(v0, v1, v2, v3);
        sums[i] = (v0 + v1) + (v2 + v3);
        ssqs[i] = fmaf(v0, v0, fmaf(v1, v1, fmaf(v2, v2, v3 * v3)));
    }
    #pragma unroll
    for (int off = 8; off >= 1; off >>= 1) {
        #pragma unroll
        for (int i = 0; i < 4; i++) {
            sums[i] += __shfl_xor_sync(0xffffffffu, sums[i], off);
            ssqs[i] += __shfl_xor_sync(0xffffffffu, ssqs[i], off);
        }
    }
    if ((t & 15) == 0) {
        #pragma unroll
        for (int i = 0; i < 4; i++) {
            atomicAdd(&g_sum1[d0 + i], sums[i]);
            atomicAdd(&g_ssq1[d0 + i], ssqs[i]);
        }
    }
}

// ---------------- K3: Z2[b] = relu(bn1(G1[b])) @ W2^T  (bn coeffs computed inline) ---
__global__ void k_gemm2(const float* __restrict__ W2, const float* __restrict__ g1,
                        const float* __restrict__ be1) {
    __shared__ float a1s[64], c1s[64];
    __shared__ __align__(16) float G1s[4096];
    __shared__ __align__(16) float W2t[64 * 36];   // W2t[o][j], j padded to 36
    int b = blockIdx.x, t = threadIdx.x;
    if (t < 64) {
        const float invn = 1.0f / (float)(B_ * C1);
        float m = g_sum1[t] * invn;
        float v = g_ssq1[t] * invn - m * m;
        float aa = g1[t] * rsqrtf(v + 1e-5f);
        a1s[t] = aa;
        c1s[t] = be1[t] - m * aa;
    }
    __syncthreads();
    const float* src = g_G1 + (size_t)b * 4096;
    for (int i = t; i < 4096; i += 256) {
        int d = i >> 6;
        G1s[i] = fmaxf(fmaf(src[i], a1s[d], c1s[d]), 0.f);
    }
    for (int i = t; i < 2048; i += 256) {
        int j = i >> 6, o = i & 63;
        W2t[o * 36 + j] = W2[i];
    }
    __syncthreads();
    int d0 = (t >> 3) * 2, j0 = (t & 7) * 4;
    float acc[2][4] = {};
    #pragma unroll 4
    for (int o = 0; o < 64; o++) {
        float4 w = *reinterpret_cast<const float4*>(&W2t[o * 36 + j0]);
        float gA = G1s[d0 * 64 + o];
        float gB = G1s[d0 * 64 + 64 + o];
        acc[0][0] = fmaf(gA, w.x, acc[0][0]); acc[0][1] = fmaf(gA, w.y, acc[0][1]);
        acc[0][2] = fmaf(gA, w.z, acc[0][2]); acc[0][3] = fmaf(gA, w.w, acc[0][3]);
        acc[1][0] = fmaf(gB, w.x, acc[1][0]); acc[1][1] = fmaf(gB, w.y, acc[1][1]);
        acc[1][2] = fmaf(gB, w.z, acc[1][2]); acc[1][3] = fmaf(gB, w.w, acc[1][3]);
    }
    float* out = g_Z2 + (size_t)b * 2048;
    *reinterpret_cast<float4*>(&out[d0 * 32 + j0]) =
        make_float4(acc[0][0], acc[0][1], acc[0][2], acc[0][3]);
    *reinterpret_cast<float4*>(&out[(d0 + 1) * 32 + j0]) =
        make_float4(acc[1][0], acc[1][1], acc[1][2], acc[1][3]);
}

// ---------------- K4: G2[b] = P @ Z2[b] + b2, with BN2 stats epilogue ----------------
__global__ void k_pgemm2(const float* __restrict__ b2) {
    __shared__ __align__(16) float Ps[4096];
    __shared__ __align__(16) float Zs[2048];
    int b = blockIdx.x, t = threadIdx.x;
    const float* src = g_Z2 + (size_t)b * 2048;
    for (int i = t; i < 4096; i += 256) Ps[i] = g_P[i];
    for (int i = t; i < 2048; i += 256) Zs[i] = src[i];
    __syncthreads();
    int d0 = (t >> 4) * 4, j0 = (t & 15) * 2;
    float acc[4][2] = {};
    #pragma unroll 4
    for (int s = 0; s < 64; s++) {
        float2 z = *reinterpret_cast<const float2*>(&Zs[s * 32 + j0]);
        #pragma unroll
        for (int i = 0; i < 4; i++) {
            float p = Ps[(d0 + i) * 64 + s];
            acc[i][0] = fmaf(p, z.x, acc[i][0]);
            acc[i][1] = fmaf(p, z.y, acc[i][1]);
        }
    }
    float2 bb = *reinterpret_cast<const float2*>(&b2[j0]);
    float* out = g_G2 + (size_t)b * 2048;
    float sums[4], ssqs[4];
    #pragma unroll
    for (int i = 0; i < 4; i++) {
        float v0 = acc[i][0] + bb.x, v1 = acc[i][1] + bb.y;
        *reinterpret_cast<float2*>(&out[(d0 + i) * 32 + j0]) = make_float2(v0, v1);
        sums[i] = v0 + v1;
        ssqs[i] = fmaf(v0, v0, v1 * v1);
    }
    #pragma unroll
    for (int off = 8; off >= 1; off >>= 1) {
        #pragma unroll
        for (int i = 0; i < 4; i++) {
            sums[i] += __shfl_xor_sync(0xffffffffu, sums[i], off);
            ssqs[i] += __shfl_xor_sync(0xffffffffu, ssqs[i], off);
        }
    }
    if ((t & 15) == 0) {
        #pragma unroll
        for (int i = 0; i < 4; i++) {
            atomicAdd(&g_sum2[d0 + i], sums[i]);
            atomicAdd(&g_ssq2[d0 + i], ssqs[i]);
        }
    }
}

// ---------------- K5: bn2 (inline coeffs) + relu + max-pool over nodes ----------------
__global__ void k_pool(const float* __restrict__ g2, const float* __restrict__ be2) {
    __shared__ float a2s[64], c2s[64];
    int t = threadIdx.x;
    if (t < 64) {
        const float invn = 1.0f / (float)(B_ * C2);
        float m = g_sum2[t] * invn;
        float v = g_ssq2[t] * invn - m * m;
        float aa = g2[t] * rsqrtf(v + 1e-5f);
        a2s[t] = aa;
        c2s[t] = be2[t] - m * aa;
    }
    __syncthreads();
    int bl = t >> 5, j = t & 31;
    int b = blockIdx.x * 8 + bl;
    const float* src = g_G2 + (size_t)b * 2048 + j;
    float m = 0.f;   // relu outputs are >= 0
    #pragma unroll 8
    for (int d = 0; d < 64; d++) {
        float v = fmaxf(fmaf(src[d * 32], a2s[d], c2s[d]), 0.f);
        m = fmaxf(m, v);
    }
    g_pool[b * 32 + j] = m;
}

// ---------------- MLP1 (scalar, 128x64 tile, 8x4/thread): H1 = relu(xf@Wl1^T+bl1) ----
__global__ __launch_bounds__(256)
void k_mlp1(const float* __restrict__ A, const float* __restrict__ Bw,
            const float* __restrict__ bias) {
    __shared__ __align__(16) float As[16 * 132];   // As[k][m], m=128 padded to 132
    __shared__ __align__(16) float Bs[16 * 68];    // Bs[k][n], n=64 padded to 68
    int t = threadIdx.x;
    int m0 = blockIdx.x * 128, n0 = blockIdx.y * 64;
    int tm = (t >> 4) * 8, tn = (t & 15) * 4;
    float acc[8][4] = {};
    for (int k0 = 0; k0 < DFP; k0 += 16) {
        #pragma unroll
        for (int rep = 0; rep < 8; rep++) {
            int i = t + rep * 256;          // 0..2047
            int r = i >> 4, kk = i & 15;
            As[kk * 132 + r] = A[(size_t)(m0 + r) * DFP + k0 + kk];
        }
        #pragma unroll
        for (int rep = 0; rep < 4; rep++) {
            int i = t + rep * 256;          // 0..1023
            int r = i >> 4, kk = i & 15;
            float bv = (n0 + r < H1D) ? Bw[(size_t)(n0 + r) * DFP + k0 + kk] : 0.f;
            Bs[kk * 68 + r] = bv;
        }
        __syncthreads();
        #pragma unroll
        for (int kk = 0; kk < 16; kk++) {
            float4 a0 = *reinterpret_cast<const float4*>(&As[kk * 132 + tm]);
            float4 a1 = *reinterpret_cast<const float4*>(&As[kk * 132 + tm + 4]);
            float4 b  = *reinterpret_cast<const float4*>(&Bs[kk * 68 + tn]);
            acc[0][0] = fmaf(a0.x, b.x, acc[0][0]); acc[0][1] = fmaf(a0.x, b.y, acc[0][1]);
            acc[0][2] = fmaf(a0.x, b.z, acc[0][2]); acc[0][3] = fmaf(a0.x, b.w, acc[0][3]);
            acc[1][0] = fmaf(a0.y, b.x, acc[1][0]); acc[1][1] = fmaf(a0.y, b.y, acc[1][1]);
            acc[1][2] = fmaf(a0.y, b.z, acc[1][2]); acc[1][3] = fmaf(a0.y, b.w, acc[1][3]);
            acc[2][0] = fmaf(a0.z, b.x, acc[2][0]); acc[2][1] = fmaf(a0.z, b.y, acc[2][1]);
            acc[2][2] = fmaf(a0.z, b.z, acc[2][2]); acc[2][3] = fmaf(a0.z, b.w, acc[2][3]);
            acc[3][0] = fmaf(a0.w, b.x, acc[3][0]); acc[3][1] = fmaf(a0.w, b.y, acc[3][1]);
            acc[3][2] = fmaf(a0.w, b.z, acc[3][2]); acc[3][3] = fmaf(a0.w, b.w, acc[3][3]);
            acc[4][0] = fmaf(a1.x, b.x, acc[4][0]); acc[4][1] = fmaf(a1.x, b.y, acc[4][1]);
            acc[4][2] = fmaf(a1.x, b.z, acc[4][2]); acc[4][3] = fmaf(a1.x, b.w, acc[4][3]);
            acc[5][0] = fmaf(a1.y, b.x, acc[5][0]); acc[5][1] = fmaf(a1.y, b.y, acc[5][1]);
            acc[5][2] = fmaf(a1.y, b.z, acc[5][2]); acc[5][3] = fmaf(a1.y, b.w, acc[5][3]);
            acc[6][0] = fmaf(a1.z, b.x, acc[6][0]); acc[6][1] = fmaf(a1.z, b.y, acc[6][1]);
            acc[6][2] = fmaf(a1.z, b.z, acc[6][2]); acc[6][3] = fmaf(a1.z, b.w, acc[6][3]);
            acc[7][0] = fmaf(a1.w, b.x, acc[7][0]); acc[7][1] = fmaf(a1.w, b.y, acc[7][1]);
            acc[7][2] = fmaf(a1.w, b.z, acc[7][2]); acc[7][3] = fmaf(a1.w, b.w, acc[7][3]);
        }
        __syncthreads();
    }
    #pragma unroll
    for (int i = 0; i < 8; i++) {
        int row = m0 + tm + i;
        float* c = g_H1 + (size_t)row * H1D;
        #pragma unroll
        for (int j = 0; j < 4; j++) {
            int col = n0 + tn + j;
            if (col < H1D) c[col] = fmaxf(acc[i][j] + __ldg(&bias[col]), 0.f);
        }
    }
}

// ---------------- MLP2 (scalar 64x64): H2 = relu(H1 @ Wl2^T + bl2) ----------------
__global__ void k_mlp2(const float* __restrict__ Bw, const float* __restrict__ bias) {
    __shared__ __align__(16) float As[16 * 68];
    __shared__ __align__(16) float Bs[16 * 68];
    const float* A = g_H1;
    float* C = g_H2;
    int m0 = blockIdx.x * 64;
    int t = threadIdx.x;
    int tm = (t >> 4) * 4, tn = (t & 15) * 4;
    float acc[4][4] = {};
    for (int k0 = 0; k0 < H1D; k0 += 16) {
        for (int i = t; i < 1024; i += 256) {
            int r = i >> 4, kk = i & 15;
            As[kk * 68 + r] = A[(size_t)(m0 + r) * H1D + k0 + kk];
            Bs[kk * 68 + r] = Bw[(size_t)r * H1D + k0 + kk];
        }
        __syncthreads();
        #pragma unroll
        for (int kk = 0; kk < 16; kk++) {
            float4 a = *reinterpret_cast<const float4*>(&As[kk * 68 + tm]);
            float4 b = *reinterpret_cast<const float4*>(&Bs[kk * 68 + tn]);
            acc[0][0] = fmaf(a.x, b.x, acc[0][0]); acc[0][1] = fmaf(a.x, b.y, acc[0][1]);
            acc[0][2] = fmaf(a.x, b.z, acc[0][2]); acc[0][3] = fmaf(a.x, b.w, acc[0][3]);
            acc[1][0] = fmaf(a.y, b.x, acc[1][0]); acc[1][1] = fmaf(a.y, b.y, acc[1][1]);
            acc[1][2] = fmaf(a.y, b.z, acc[1][2]); acc[1][3] = fmaf(a.y, b.w, acc[1][3]);
            acc[2][0] = fmaf(a.z, b.x, acc[2][0]); acc[2][1] = fmaf(a.z, b.y, acc[2][1]);
            acc[2][2] = fmaf(a.z, b.z, acc[2][2]); acc[2][3] = fmaf(a.z, b.w, acc[2][3]);
            acc[3][0] = fmaf(a.w, b.x, acc[3][0]); acc[3][1] = fmaf(a.w, b.y, acc[3][1]);
            acc[3][2] = fmaf(a.w, b.z, acc[3][2]); acc[3][3] = fmaf(a.w, b.w, acc[3][3]);
        }
        __syncthreads();
    }
    #pragma unroll
    for (int i = 0; i < 4; i++) {
        int row = m0 + tm + i;
        #pragma unroll
        for (int j = 0; j < 4; j++) {
            int col = tn + j;
            C[(size_t)row * H2D + col] = fmaxf(acc[i][j] + __ldg(&bias[col]), 0.f);
        }
    }
}

// ---------------- final: out = [pool, H2] @ Wfc^T + bfc ----------------
__global__ void k_final(const float* __restrict__ Wfc, const float* __restrict__ bfc,
                        float* __restrict__ out) {
    __shared__ float Ws[192];
    int t = threadIdx.x;
    if (t < 192) Ws[t] = Wfc[t];
    __syncthreads();
    int b = blockIdx.x * 256 + t;
    float a0 = __ldg(&bfc[0]), a1 = __ldg(&bfc[1]);
    const float* pp = g_pool + b * 32;
    const float* hh = g_H2 + b * 64;
    #pragma unroll
    for (int j = 0; j < 32; j++) {
        float v = pp[j];
        a0 = fmaf(v, Ws[j], a0);
        a1 = fmaf(v, Ws[96 + j], a1);
    }
    #pragma unroll
    for (int j = 0; j < 64; j++) {
        float v = hh[j];
        a0 = fmaf(v, Ws[32 + j], a0);
        a1 = fmaf(v, Ws[128 + j], a1);
    }
    out[b * 2]     = a0;
    out[b * 2 + 1] = a1;
}

// ---------------- launch ----------------
extern "C" void kernel_launch(void* const* d_in, const int* in_sizes, int n_in,
                              void* d_out, int out_size) {
    const float* xf  = (const float*)d_in[0];
    const float* xn  = (const float*)d_in[1];
    const int*   el  = (const int*)  d_in[2];
    const float* W1  = (const float*)d_in[3];
    const float* b1  = (const float*)d_in[4];
    const float* g1  = (const float*)d_in[5];
    const float* be1 = (const float*)d_in[6];
    const float* W2  = (const float*)d_in[7];
    const float* b2  = (const float*)d_in[8];
    const float* g2  = (const float*)d_in[9];
    const float* be2 = (const float*)d_in[10];
    const float* Wl1 = (const float*)d_in[11];
    const float* bl1 = (const float*)d_in[12];
    const float* Wl2 = (const float*)d_in[13];
    const float* bl2 = (const float*)d_in[14];
    const float* Wfc = (const float*)d_in[15];
    const float* bfc = (const float*)d_in[16];
    float* out = (float*)d_out;

    k_prep<<<1, 256>>>(el);

    // graph path (BN stats fused into pgemm epilogues; coeffs computed inline)
    k_gemm1<<<(B_ * NNODE) / 64, 256>>>(xn, W1);
    k_pgemm1<<<B_, 256>>>(b1);
    k_gemm2<<<B_, 256>>>(W2, g1, be1);
    k_pgemm2<<<B_, 256>>>(b2);
    k_pool<<<B_ / 8, 256>>>(g2, be2);

    // fingerprint MLP path
    k_mlp1<<<dim3(B_ / 128, (H1D + 63) / 64), 256>>>(xf, Wl1, bl1);
    k_mlp2<<<B_ / 64, 256>>>(Wl2, bl2);

    k_final<<<B_ / 256, 256>>>(Wfc, bfc, out);
}